// round 15
// baseline (speedup 1.0000x reference)
#include <cuda_runtime.h>
#include <math.h>

// ---------------- problem constants ----------------
#define G_NUM 50
#define NPER  1000
#define HDIM  128
#define K1    600
#define K2    360
#define K3    216
#define N1    (G_NUM*NPER)   // 50000
#define N2    (G_NUM*K1)     // 30000
#define N3    (G_NUM*K2)     // 18000
#define N4    (G_NUM*K3)     // 10800
#define CAP   96             // max in-degree bucket (Poisson(16); P(>=96) ~ 1e-44)
#define FINF  3.402823466e38f
#define SEG   512            // per-warp survivor-list segment (warp sees <=512 edges)

// ---------------- scratch (device globals; no allocation allowed) ----------------
__device__ float g_hl[(size_t)N1*HDIM];   // linear features  h = x @ W^T
__device__ float g_h [(size_t)N1*HDIM];   // GAT output (post relu)
__device__ float g_as[N1];
__device__ float g_ad[N1];
__device__ float g_sc[N1];
__device__ int   g_deg[N1];
__device__ __align__(16) int g_adj[(size_t)N1*CAP];
__device__ __align__(16) int2 g_list[(size_t)G_NUM*32*SEG];  // per-warp segments
__device__ int   g_cnt[G_NUM*32];
__device__ int   g_permA[N2];             // new-id -> old global row in h
__device__ float g_gscA[N2];              // tanh(score) gate per new id
__device__ float g_z[G_NUM*256];
__device__ float g_norms[2];

// monotone float->uint key (descending top-k = largest keys)
__device__ __forceinline__ unsigned f2key(float f) {
    unsigned u = __float_as_uint(f);
    return (u & 0x80000000u) ? ~u : (u | 0x80000000u);
}

// ---------------- init: norms (block 0, warp 0) + stage-1 adjacency build ----------
__global__ void init_k(const float* __restrict__ p1, const float* __restrict__ p2,
                       float* __restrict__ nrm,
                       const int* __restrict__ src, const int* __restrict__ dst,
                       int E, int* __restrict__ deg, int* __restrict__ adj)
{
    int t = threadIdx.x;
    if (blockIdx.x == 0 && t < 32) {
        int lane = t;
        float s1 = 0.f, s2 = 0.f;
        #pragma unroll
        for (int j = 0; j < 4; j++) {
            float v1 = p1[lane*4 + j], v2 = p2[lane*4 + j];
            s1 += v1*v1; s2 += v2*v2;
        }
        #pragma unroll
        for (int o = 16; o > 0; o >>= 1) {
            s1 += __shfl_xor_sync(0xffffffffu, s1, o);
            s2 += __shfl_xor_sync(0xffffffffu, s2, o);
        }
        if (lane == 0) { nrm[0] = rsqrtf(s1); nrm[1] = rsqrtf(s2); }
    }
    int base = (blockIdx.x*blockDim.x + t)*4;
    int s_[4], d_[4]; int cnt = 0;
    #pragma unroll
    for (int q = 0; q < 4; q++) {
        int e = base + q;
        if (e < E) { s_[cnt] = __ldg(src+e); d_[cnt] = __ldg(dst+e); cnt++; }
    }
    #pragma unroll
    for (int q = 0; q < 4; q++) {
        if (q < cnt) {
            int pos = atomicAdd(&deg[d_[q]], 1);
            if (pos < CAP) adj[(size_t)d_[q]*CAP + pos] = s_[q];
        }
    }
}

// ---------------- GEMM: Y[M,128] = gathered-X[M,128] @ W[128,128]^T + fused dots ----
#define LDS_X 132
#define LDS_W 132
#define GEMM_SMEM ((128*LDS_X + 128*LDS_W)*4)

__global__ void __launch_bounds__(256, 1)
gemm128_k(const float* __restrict__ X, const float* __restrict__ W,
          float* __restrict__ Y, int M,
          const float* __restrict__ aS, const float* __restrict__ aD,
          float* __restrict__ asv, float* __restrict__ adv,
          const int* __restrict__ perm, const float* __restrict__ gsc)
{
    extern __shared__ float sm[];
    float* Xs = sm;                 // [row][k]  row-major, padded
    float* Ws = sm + 128*LDS_X;     // [k][c]    transposed W
    int tid = threadIdx.x;
    int rowBase = blockIdx.x * 128;

    #pragma unroll
    for (int i = 0; i < 16; i++) {
        int v  = tid + i*256;      // 0..4095 float4 slots
        int r  = v >> 5;
        int k4 = v & 31;
        int gr = rowBase + r; if (gr >= M) gr = M - 1;
        int srcRow = gr;
        float scale = 1.f;
        if (perm) { srcRow = perm[gr]; scale = gsc[gr]; }
        float4 x4 = *reinterpret_cast<const float4*>(X + (size_t)srcRow*128 + k4*4);
        float* d = Xs + r*LDS_X + k4*4;
        d[0] = x4.x*scale; d[1] = x4.y*scale; d[2] = x4.z*scale; d[3] = x4.w*scale;
    }
    #pragma unroll
    for (int i = 0; i < 16; i++) {
        int v  = tid + i*256;
        int c  = v >> 5;
        int k4 = v & 31;
        float4 w4 = *reinterpret_cast<const float4*>(W + (size_t)c*128 + k4*4);
        Ws[(k4*4+0)*LDS_W + c] = w4.x;
        Ws[(k4*4+1)*LDS_W + c] = w4.y;
        Ws[(k4*4+2)*LDS_W + c] = w4.z;
        Ws[(k4*4+3)*LDS_W + c] = w4.w;
    }
    __syncthreads();

    int tx = tid & 15, ty = tid >> 4;   // 16x16 threads, 8 rows x 8 cols each
    float acc[8][8];
    #pragma unroll
    for (int i = 0; i < 8; i++)
        #pragma unroll
        for (int j = 0; j < 8; j++) acc[i][j] = 0.f;

    #pragma unroll 2
    for (int kk = 0; kk < 128; kk += 4) {
        float4 a4[8];
        #pragma unroll
        for (int i = 0; i < 8; i++)
            a4[i] = *reinterpret_cast<const float4*>(Xs + (ty*8 + i)*LDS_X + kk);
        #pragma unroll
        for (int q = 0; q < 4; q++) {
            float4 b0 = *reinterpret_cast<const float4*>(Ws + (kk+q)*LDS_W + tx*4);
            float4 b1 = *reinterpret_cast<const float4*>(Ws + (kk+q)*LDS_W + 64 + tx*4);
            #pragma unroll
            for (int i = 0; i < 8; i++) {
                float av = (q == 0) ? a4[i].x : (q == 1) ? a4[i].y : (q == 2) ? a4[i].z : a4[i].w;
                acc[i][0] += av*b0.x; acc[i][1] += av*b0.y;
                acc[i][2] += av*b0.z; acc[i][3] += av*b0.w;
                acc[i][4] += av*b1.x; acc[i][5] += av*b1.y;
                acc[i][6] += av*b1.z; acc[i][7] += av*b1.w;
            }
        }
    }

    float aSv[8], aDv[8];
    #pragma unroll
    for (int j = 0; j < 4; j++) {
        aSv[j]   = aS[tx*4 + j];      aSv[4+j] = aS[64 + tx*4 + j];
        aDv[j]   = aD[tx*4 + j];      aDv[4+j] = aD[64 + tx*4 + j];
    }
    int lane = tid & 31;
    #pragma unroll
    for (int i = 0; i < 8; i++) {
        int r = rowBase + ty*8 + i;
        bool ok = (r < M);
        if (ok) {
            *reinterpret_cast<float4*>(Y + (size_t)r*128 + tx*4) =
                make_float4(acc[i][0], acc[i][1], acc[i][2], acc[i][3]);
            *reinterpret_cast<float4*>(Y + (size_t)r*128 + 64 + tx*4) =
                make_float4(acc[i][4], acc[i][5], acc[i][6], acc[i][7]);
        }
        float pa = 0.f, pd = 0.f;
        #pragma unroll
        for (int j = 0; j < 8; j++) { pa += acc[i][j]*aSv[j]; pd += acc[i][j]*aDv[j]; }
        #pragma unroll
        for (int o = 8; o > 0; o >>= 1) {
            pa += __shfl_xor_sync(0xffffffffu, pa, o);
            pd += __shfl_xor_sync(0xffffffffu, pd, o);
        }
        if (ok && (lane & 15) == 0) { asv[r] = pa; adv[r] = pd; }
    }
}

// ---------------- GAT aggregation + fused pooling score ----------------
__global__ void gat_agg_k(const float* __restrict__ hl, const float* __restrict__ asv,
                          const float* __restrict__ adv, const int* __restrict__ adj,
                          const int* __restrict__ deg, const float* __restrict__ b,
                          float* __restrict__ out, int N,
                          const float* __restrict__ p, const float* __restrict__ nrm,
                          int nidx, float* __restrict__ sc)
{
    int d = (blockIdx.x*blockDim.x + threadIdx.x) >> 5;
    int lane = threadIdx.x & 31;
    if (d >= N) return;
    float add = adv[d];
    float l = asv[d] + add; l = (l > 0.f) ? l : 0.2f*l;
    float w = __expf(l);
    float den0 = w, den1 = 0.f;
    float4 hv = *reinterpret_cast<const float4*>(hl + (size_t)d*128 + lane*4);
    float4 a0 = make_float4(w*hv.x, w*hv.y, w*hv.z, w*hv.w);
    float4 a1 = make_float4(0.f, 0.f, 0.f, 0.f);
    int dg = deg[d]; if (dg > CAP) dg = CAP;
    const int* row = adj + (size_t)d*CAP;
    int j = 0;
    for (; j + 4 <= dg; j += 4) {
        int4 s4 = *reinterpret_cast<const int4*>(row + j);
        float l0 = asv[s4.x] + add; l0 = (l0 > 0.f) ? l0 : 0.2f*l0;
        float l1 = asv[s4.y] + add; l1 = (l1 > 0.f) ? l1 : 0.2f*l1;
        float l2 = asv[s4.z] + add; l2 = (l2 > 0.f) ? l2 : 0.2f*l2;
        float l3 = asv[s4.w] + add; l3 = (l3 > 0.f) ? l3 : 0.2f*l3;
        float w0 = __expf(l0), w1 = __expf(l1), w2 = __expf(l2), w3 = __expf(l3);
        float4 g0 = *reinterpret_cast<const float4*>(hl + (size_t)s4.x*128 + lane*4);
        float4 g1 = *reinterpret_cast<const float4*>(hl + (size_t)s4.y*128 + lane*4);
        float4 g2 = *reinterpret_cast<const float4*>(hl + (size_t)s4.z*128 + lane*4);
        float4 g3 = *reinterpret_cast<const float4*>(hl + (size_t)s4.w*128 + lane*4);
        den0 += w0 + w2; den1 += w1 + w3;
        a0.x += w0*g0.x; a0.y += w0*g0.y; a0.z += w0*g0.z; a0.w += w0*g0.w;
        a1.x += w1*g1.x; a1.y += w1*g1.y; a1.z += w1*g1.z; a1.w += w1*g1.w;
        a0.x += w2*g2.x; a0.y += w2*g2.y; a0.z += w2*g2.z; a0.w += w2*g2.w;
        a1.x += w3*g3.x; a1.y += w3*g3.y; a1.z += w3*g3.z; a1.w += w3*g3.w;
    }
    for (; j < dg; j++) {
        int s0 = row[j];
        float l0 = asv[s0] + add; l0 = (l0 > 0.f) ? l0 : 0.2f*l0;
        float w0 = __expf(l0);
        float4 g0 = *reinterpret_cast<const float4*>(hl + (size_t)s0*128 + lane*4);
        den0 += w0;
        a0.x += w0*g0.x; a0.y += w0*g0.y; a0.z += w0*g0.z; a0.w += w0*g0.w;
    }
    float inv = 1.f/(den0 + den1);
    float4 bb = *reinterpret_cast<const float4*>(b + lane*4);
    float4 o;
    o.x = fmaxf((a0.x + a1.x)*inv + bb.x, 0.f);
    o.y = fmaxf((a0.y + a1.y)*inv + bb.y, 0.f);
    o.z = fmaxf((a0.z + a1.z)*inv + bb.z, 0.f);
    o.w = fmaxf((a0.w + a1.w)*inv + bb.w, 0.f);
    *reinterpret_cast<float4*>(out + (size_t)d*128 + lane*4) = o;
    float4 p4 = *reinterpret_cast<const float4*>(p + lane*4);
    float s = o.x*p4.x + o.y*p4.y + o.z*p4.z + o.w*p4.w;
    #pragma unroll
    for (int off = 16; off > 0; off >>= 1) s += __shfl_xor_sync(0xffffffffu, s, off);
    if (lane == 0) sc[d] = s * nrm[nidx];
}

// ---------------- fused per-graph pool: radix-select topk + readout + build (+mlp) ---
// modes 1/2: grid = 2*G_NUM. role 0 = readout + perm/gsc emit; role 1 = adjacency build.
// mode 3:    grid = G_NUM, role 0 only; readout + final MLP, no build, no perm.
__global__ void __launch_bounds__(1024, 1)
pool_k(const float* __restrict__ sc, const float* __restrict__ h,
       float* __restrict__ z,
       const int* __restrict__ srcRaw, const int* __restrict__ dstRaw, int ePer,
       const int2* __restrict__ listIn, const int* __restrict__ cntIn,
       int2* __restrict__ listOut, int* __restrict__ cntOut,
       int* __restrict__ deg, int* __restrict__ adj,
       int* __restrict__ permOut, float* __restrict__ gscOut,
       int n, int k, int mode,
       const float* __restrict__ lw1, const float* __restrict__ lb1,
       const float* __restrict__ lw2, const float* __restrict__ lb2,
       const float* __restrict__ lw3, const float* __restrict__ lb3,
       float* __restrict__ out)
{
    __shared__ unsigned skey[1024];
    __shared__ float sval[1024];
    __shared__ int   sidx[1024];      // new-id -> old local index
    __shared__ int   smap[NPER];      // old local index -> new-id or -1
    __shared__ int   sdeg[K1];
    __shared__ float sgsc[K1];
    __shared__ int   hist8[8*256];    // round-1 sub-histograms
    __shared__ int   hist[256];
    __shared__ int   sfx[256];        // sfx[b] = #keys with bin >= b
    __shared__ int   wOff[32];
    __shared__ unsigned s_prefix;
    __shared__ int   s_need;
    __shared__ float rmax[1024], rsum[1024];
    __shared__ float zr[256], t1v[128], t2v[64], ov[10], red[2];

    int g, role;
    if (mode == 3) { g = blockIdx.x; role = 0; }
    else           { g = blockIdx.x >> 1; role = blockIdx.x & 1; }
    int t = threadIdx.x;
    int wid = t >> 5, lane = t & 31;
    unsigned lmask = (1u << lane) - 1u;

    // ---- load scores + zero round-1 sub-histograms ----
    if (t < n) {
        float v = sc[g*n + t];
        sval[t] = v;
        skey[t] = f2key(v);
        smap[t] = -1;
    } else if (t < 1024) {
        skey[t] = 0u; sval[t] = -FINF;
    }
    hist8[t] = 0; hist8[t + 1024] = 0;
    if (t < K1) sdeg[t] = 0;
    __syncthreads();

    // ---- 4-round radix select: threshold key T, tie-count need ----
    unsigned prefix = 0; int need = k;
    for (int shift = 24; shift >= 0; shift -= 8) {
        if (shift == 24) {
            if (t < n) atomicAdd(&hist8[(wid & 7)*256 + (skey[t] >> 24)], 1);
        } else {
            if (t < 256) hist[t] = 0;
            __syncthreads();
            if (t < n) {
                unsigned key = skey[t];
                if ((key >> (shift+8)) == (prefix >> (shift+8)))
                    atomicAdd(&hist[(key >> shift) & 255], 1);
            }
        }
        __syncthreads();
        // warp-0 suffix scan over 256 bins (lane owns bins [8*lane, 8*lane+8))
        if (wid == 0) {
            int base = lane*8;
            int v[8]; int cs = 0;
            #pragma unroll
            for (int j = 0; j < 8; j++) {
                int hv;
                if (shift == 24) {
                    hv = 0;
                    #pragma unroll
                    for (int s8 = 0; s8 < 8; s8++) hv += hist8[s8*256 + base + j];
                } else hv = hist[base + j];
                v[j] = hv; cs += hv;
            }
            int suf = cs;
            #pragma unroll
            for (int o = 1; o < 32; o <<= 1) {
                int u = __shfl_down_sync(0xffffffffu, suf, o);
                if (lane + o < 32) suf += u;
            }
            int run = suf - cs;          // sum over lanes > lane
            #pragma unroll
            for (int j = 7; j >= 0; j--) { run += v[j]; sfx[base + j] = run; }
        }
        __syncthreads();
        if (t < 256) {
            int b = t;
            int Sb  = sfx[b];                       // keys with bin >= b
            int Sb1 = (b == 255) ? 0 : sfx[b + 1];  // keys with bin >  b
            if (Sb1 < need && need <= Sb) {
                s_prefix = prefix | ((unsigned)b << shift);
                s_need   = need - Sb1;
            }
        }
        __syncthreads();
        prefix = s_prefix; need = s_need;
        __syncthreads();
    }
    const unsigned T = prefix;

    // ---- deterministic selection: key>T, plus first `need` key==T by index ----
    bool eq = false, gt = false;
    if (t < n) {
        unsigned key = skey[t];
        gt = (key > T);
        eq = (key == T);
    }
    unsigned beq = __ballot_sync(0xffffffffu, eq);
    int eqInWarp = __popc(beq & lmask);
    if (lane == 0) wOff[wid] = __popc(beq);
    __syncthreads();
    if (wid == 0) {
        int v = wOff[lane];
        int inc = v;
        #pragma unroll
        for (int o = 1; o < 32; o <<= 1) {
            int u = __shfl_up_sync(0xffffffffu, inc, o);
            if (lane >= o) inc += u;
        }
        wOff[lane] = inc - v;
    }
    __syncthreads();
    int tieRank = wOff[wid] + eqInWarp;
    bool sel = gt || (eq && tieRank < need);
    __syncthreads();

    unsigned bsel = __ballot_sync(0xffffffffu, sel);
    int selInWarp = __popc(bsel & lmask);
    if (lane == 0) wOff[wid] = __popc(bsel);
    __syncthreads();
    if (wid == 0) {
        int v = wOff[lane];
        int inc = v;
        #pragma unroll
        for (int o = 1; o < 32; o <<= 1) {
            int u = __shfl_up_sync(0xffffffffu, inc, o);
            if (lane >= o) inc += u;
        }
        wOff[lane] = inc - v;
    }
    __syncthreads();
    if (sel) {
        int newid = wOff[wid] + selInWarp;   // 0..k-1, index-ordered
        smap[t] = newid;
        sidx[newid] = t;
        sgsc[newid] = tanhf(sval[t]);
    }
    __syncthreads();

    if (role == 0) {
        // ---- emit perm/gsc for the next GEMM's fused gather (modes 1,2) ----
        if (mode != 3 && t < k) {
            permOut[g*k + t] = g*n + sidx[t];
            gscOut[g*k + t]  = sgsc[t];
        }

        // ---- readout directly from h * gsc: columns 0..127, 8 row-chunks ----
        {
            int c = t & 127, ch = t >> 7;
            int per = (k + 7) >> 3;
            int r0 = ch*per, r1 = r0 + per; if (r1 > k) r1 = k;
            float m = -FINF, s = 0.f;
            for (int r = r0; r < r1; r++) {
                float v = h[((size_t)(g*n + sidx[r]))*128 + c] * sgsc[r];
                m = fmaxf(m, v); s += v;
            }
            rmax[ch*128 + c] = m; rsum[ch*128 + c] = s;
        }
        __syncthreads();
        if (t < 128) {
            float m = -FINF, s = 0.f;
            #pragma unroll
            for (int ch = 0; ch < 8; ch++) { m = fmaxf(m, rmax[ch*128 + t]); s += rsum[ch*128 + t]; }
            if (mode == 1) {
                z[g*256 + t]       = m;
                z[g*256 + 128 + t] = s / (float)k;
            } else {
                z[g*256 + t]       += m;
                z[g*256 + 128 + t] += s / (float)k;
            }
        }
        if (mode == 3) {
            // ---- final MLP + log_softmax ----
            __syncthreads();
            if (t < 256) zr[t] = z[g*256 + t];
            __syncthreads();
            if (t < 128) {
                float a = lb1[t];
                const float* w = lw1 + t*256;
                for (int j = 0; j < 256; j++) a += zr[j]*w[j];
                t1v[t] = fmaxf(a, 0.f);
            }
            __syncthreads();
            if (t < 64) {
                float a = lb2[t];
                const float* w = lw2 + t*128;
                for (int j = 0; j < 128; j++) a += t1v[j]*w[j];
                t2v[t] = fmaxf(a, 0.f);
            }
            __syncthreads();
            if (t < 10) {
                float a = lb3[t];
                const float* w = lw3 + t*64;
                for (int j = 0; j < 64; j++) a += t2v[j]*w[j];
                ov[t] = a;
            }
            __syncthreads();
            if (t == 0) {
                float m = -FINF;
                for (int i = 0; i < 10; i++) m = fmaxf(m, ov[i]);
                float s = 0.f;
                for (int i = 0; i < 10; i++) s += expf(ov[i] - m);
                red[0] = m; red[1] = logf(s);
            }
            __syncthreads();
            if (t < 10) out[g*10 + t] = ov[t] - red[0] - red[1];
        }
    } else if (mode == 1) {
        // ---- raw-edge build + per-warp survivor-list segments (no smem atomics) ----
        int base = g*ePer;
        int2* seg = listOut + ((size_t)(g*32 + wid))*SEG;
        int lc = 0;                        // per-warp segment fill (uniform across warp)
        int iters = (ePer + 1023) >> 10;   // uniform trip count for ALL threads
        for (int it = 0; it < iters; it++) {
            int e0 = t + (it << 10);
            bool act = (e0 < ePer);
            int sn = -1, dn = -1;
            if (act) {
                int s = srcRaw[base + e0] - g*n;
                int d = dstRaw[base + e0] - g*n;
                sn = smap[s]; dn = smap[d];
            }
            bool ok = act && sn >= 0 && dn >= 0;
            if (ok) {
                int pos = atomicAdd(&sdeg[dn], 1);
                if (pos < CAP) adj[((size_t)(g*k + dn))*CAP + pos] = g*k + sn;
            }
            unsigned mask = __ballot_sync(0xffffffffu, ok);
            if (ok) {
                int off = lc + __popc(mask & lmask);
                if (off < SEG) seg[off] = make_int2(sn, dn);
            }
            lc += __popc(mask);
        }
        if (lane == 0) cntOut[g*32 + wid] = (lc < SEG) ? lc : SEG;
        __syncthreads();
        if (t < k) deg[g*k + t] = sdeg[t];
    } else {
        // ---- mode 2: per-warp-segment list build ----
        for (int sgi = 0; sgi < 32; sgi++) {
            int cnt = cntIn[g*32 + sgi];
            const int2* seg = listIn + ((size_t)(g*32 + sgi))*SEG;
            for (int e = t; e < cnt; e += 1024) {
                int2 sd = seg[e];
                int sn = smap[sd.x], dn = smap[sd.y];
                if (sn >= 0 && dn >= 0) {
                    int pos = atomicAdd(&sdeg[dn], 1);
                    if (pos < CAP) adj[((size_t)(g*k + dn))*CAP + pos] = g*k + sn;
                }
            }
        }
        __syncthreads();
        if (t < k) deg[g*k + t] = sdeg[t];
    }
}

// ---------------- host driver ----------------
static inline int cdiv(int a, int b) { return (a + b - 1) / b; }

extern "C" void kernel_launch(void* const* d_in, const int* in_sizes, int n_in,
                              void* d_out, int out_size)
{
    const float* x   = (const float*)d_in[0];
    const int*   ei  = (const int*)  d_in[1];
    const float* W1  = (const float*)d_in[2];
    const float* aS1 = (const float*)d_in[3];
    const float* aD1 = (const float*)d_in[4];
    const float* b1  = (const float*)d_in[5];
    const float* W2  = (const float*)d_in[6];
    const float* aS2 = (const float*)d_in[7];
    const float* aD2 = (const float*)d_in[8];
    const float* b2  = (const float*)d_in[9];
    const float* W3  = (const float*)d_in[10];
    const float* aS3 = (const float*)d_in[11];
    const float* aD3 = (const float*)d_in[12];
    const float* b3  = (const float*)d_in[13];
    const float* p1  = (const float*)d_in[14];
    const float* p2  = (const float*)d_in[15];
    const float* lw1 = (const float*)d_in[16];
    const float* lb1 = (const float*)d_in[17];
    const float* lw2 = (const float*)d_in[18];
    const float* lb2 = (const float*)d_in[19];
    const float* lw3 = (const float*)d_in[20];
    const float* lb3 = (const float*)d_in[21];
    float* out = (float*)d_out;

    const int E = in_sizes[1] / 2;
    const int EPER = E / G_NUM;

    void *p_hl, *p_h, *p_as, *p_ad, *p_sc, *p_deg, *p_adj;
    void *p_list, *p_cnt, *p_perm, *p_gsc, *p_z, *p_nrm;
    cudaGetSymbolAddress(&p_hl, g_hl);   cudaGetSymbolAddress(&p_h, g_h);
    cudaGetSymbolAddress(&p_as, g_as);   cudaGetSymbolAddress(&p_ad, g_ad);
    cudaGetSymbolAddress(&p_sc, g_sc);
    cudaGetSymbolAddress(&p_deg, g_deg); cudaGetSymbolAddress(&p_adj, g_adj);
    cudaGetSymbolAddress(&p_list, g_list); cudaGetSymbolAddress(&p_cnt, g_cnt);
    cudaGetSymbolAddress(&p_perm, g_permA); cudaGetSymbolAddress(&p_gsc, g_gscA);
    cudaGetSymbolAddress(&p_z, g_z);       cudaGetSymbolAddress(&p_nrm, g_norms);

    float* hl  = (float*)p_hl;  float* h   = (float*)p_h;
    float* asv = (float*)p_as;  float* adv = (float*)p_ad;  float* sc = (float*)p_sc;
    int* deg = (int*)p_deg;     int* adj = (int*)p_adj;
    int2* lst = (int2*)p_list;  int* cnt = (int*)p_cnt;
    int* perm = (int*)p_perm;   float* gsc = (float*)p_gsc;
    float* z = (float*)p_z;     float* nrm = (float*)p_nrm;

    cudaFuncSetAttribute(gemm128_k, cudaFuncAttributeMaxDynamicSharedMemorySize, GEMM_SMEM);

    const int EB = cdiv(E, 1024);

    // ---------- stage 1 ----------
    cudaMemsetAsync(deg, 0, (size_t)N1*sizeof(int));
    init_k<<<EB, 256>>>(p1, p2, nrm, ei, ei + E, E, deg, adj);
    gemm128_k<<<cdiv(N1, 128), 256, GEMM_SMEM>>>(x, W1, hl, N1, aS1, aD1, asv, adv,
                                                 nullptr, nullptr);
    gat_agg_k<<<cdiv(N1, 8), 256>>>(hl, asv, adv, adj, deg, b1, h, N1, p1, nrm, 0, sc);
    pool_k<<<2*G_NUM, 1024>>>(sc, h, z, ei, ei + E, EPER,
                              nullptr, nullptr, lst, cnt, deg, adj, perm, gsc,
                              NPER, K1, 1,
                              lw1, lb1, lw2, lb2, lw3, lb3, nullptr);

    // ---------- stage 2 ----------
    gemm128_k<<<cdiv(N2, 128), 256, GEMM_SMEM>>>(h, W2, hl, N2, aS2, aD2, asv, adv,
                                                 perm, gsc);
    gat_agg_k<<<cdiv(N2, 8), 256>>>(hl, asv, adv, adj, deg, b2, h, N2, p2, nrm, 1, sc);
    pool_k<<<2*G_NUM, 1024>>>(sc, h, z, nullptr, nullptr, EPER,
                              lst, cnt, nullptr, nullptr, deg, adj, perm, gsc,
                              K1, K2, 2,
                              lw1, lb1, lw2, lb2, lw3, lb3, nullptr);

    // ---------- stage 3 ----------
    gemm128_k<<<cdiv(N3, 128), 256, GEMM_SMEM>>>(h, W3, hl, N3, aS3, aD3, asv, adv,
                                                 perm, gsc);
    gat_agg_k<<<cdiv(N3, 8), 256>>>(hl, asv, adv, adj, deg, b3, h, N3, p2, nrm, 1, sc);
    pool_k<<<G_NUM, 1024>>>(sc, h, z, nullptr, nullptr, EPER,
                            nullptr, nullptr, nullptr, nullptr, nullptr, nullptr,
                            nullptr, nullptr,
                            K2, K3, 3,
                            lw1, lb1, lw2, lb2, lw3, lb3, out);
}

// round 16
// speedup vs baseline: 1.0538x; 1.0538x over previous
#include <cuda_runtime.h>
#include <math.h>

// ---------------- problem constants ----------------
#define G_NUM 50
#define NPER  1000
#define HDIM  128
#define K1    600
#define K2    360
#define K3    216
#define N1    (G_NUM*NPER)   // 50000
#define N2    (G_NUM*K1)     // 30000
#define N3    (G_NUM*K2)     // 18000
#define N4    (G_NUM*K3)     // 10800
#define CAP   96             // max in-degree bucket (Poisson(16); P(>=96) ~ 1e-44)
#define FINF  3.402823466e38f
#define SEG   512            // per-warp survivor-list segment (warp sees <=512 edges)

// ---------------- scratch (device globals; no allocation allowed) ----------------
__device__ float g_hl[(size_t)N1*HDIM];   // linear features  h = x @ W^T
__device__ float g_h [(size_t)N1*HDIM];   // GAT output (post relu)
__device__ float g_as[N1];
__device__ float g_ad[N1];
__device__ float g_sc[N1];
__device__ int   g_deg[N1];
__device__ __align__(16) int g_adj[(size_t)N1*CAP];
__device__ __align__(16) int2 g_list[(size_t)G_NUM*32*SEG];  // per-warp segments
__device__ int   g_cnt[G_NUM*32];
__device__ int   g_permA[N2];             // new-id -> old global row in h
__device__ float g_gscA[N2];              // tanh(score) gate per new id
__device__ float g_z[G_NUM*256];
__device__ float g_norms[2];

// monotone float->uint key (descending top-k = largest keys)
__device__ __forceinline__ unsigned f2key(float f) {
    unsigned u = __float_as_uint(f);
    return (u & 0x80000000u) ? ~u : (u | 0x80000000u);
}

// ---------------- init: norms (block 0, warp 0) + stage-1 adjacency build ----------
__global__ void init_k(const float* __restrict__ p1, const float* __restrict__ p2,
                       float* __restrict__ nrm,
                       const int* __restrict__ src, const int* __restrict__ dst,
                       int E, int* __restrict__ deg, int* __restrict__ adj)
{
    int t = threadIdx.x;
    if (blockIdx.x == 0 && t < 32) {
        int lane = t;
        float s1 = 0.f, s2 = 0.f;
        #pragma unroll
        for (int j = 0; j < 4; j++) {
            float v1 = p1[lane*4 + j], v2 = p2[lane*4 + j];
            s1 += v1*v1; s2 += v2*v2;
        }
        #pragma unroll
        for (int o = 16; o > 0; o >>= 1) {
            s1 += __shfl_xor_sync(0xffffffffu, s1, o);
            s2 += __shfl_xor_sync(0xffffffffu, s2, o);
        }
        if (lane == 0) { nrm[0] = rsqrtf(s1); nrm[1] = rsqrtf(s2); }
    }
    int base = (blockIdx.x*blockDim.x + t)*4;
    int s_[4], d_[4]; int cnt = 0;
    #pragma unroll
    for (int q = 0; q < 4; q++) {
        int e = base + q;
        if (e < E) { s_[cnt] = __ldg(src+e); d_[cnt] = __ldg(dst+e); cnt++; }
    }
    #pragma unroll
    for (int q = 0; q < 4; q++) {
        if (q < cnt) {
            int pos = atomicAdd(&deg[d_[q]], 1);
            if (pos < CAP) adj[(size_t)d_[q]*CAP + pos] = s_[q];
        }
    }
}

// ---------------- GEMM: Y[M,128] = gathered-X[M,128] @ W[128,128]^T + fused dots ----
#define LDS_X 132
#define LDS_W 132
#define GEMM_SMEM ((128*LDS_X + 128*LDS_W)*4)

__global__ void __launch_bounds__(256, 1)
gemm128_k(const float* __restrict__ X, const float* __restrict__ W,
          float* __restrict__ Y, int M,
          const float* __restrict__ aS, const float* __restrict__ aD,
          float* __restrict__ asv, float* __restrict__ adv,
          const int* __restrict__ perm, const float* __restrict__ gsc)
{
    extern __shared__ float sm[];
    float* Xs = sm;                 // [row][k]  row-major, padded
    float* Ws = sm + 128*LDS_X;     // [k][c]    transposed W
    int tid = threadIdx.x;
    int rowBase = blockIdx.x * 128;

    #pragma unroll
    for (int i = 0; i < 16; i++) {
        int v  = tid + i*256;      // 0..4095 float4 slots
        int r  = v >> 5;
        int k4 = v & 31;
        int gr = rowBase + r; if (gr >= M) gr = M - 1;
        int srcRow = gr;
        float scale = 1.f;
        if (perm) { srcRow = perm[gr]; scale = gsc[gr]; }
        float4 x4 = *reinterpret_cast<const float4*>(X + (size_t)srcRow*128 + k4*4);
        float* d = Xs + r*LDS_X + k4*4;
        d[0] = x4.x*scale; d[1] = x4.y*scale; d[2] = x4.z*scale; d[3] = x4.w*scale;
    }
    #pragma unroll
    for (int i = 0; i < 16; i++) {
        int v  = tid + i*256;
        int c  = v >> 5;
        int k4 = v & 31;
        float4 w4 = *reinterpret_cast<const float4*>(W + (size_t)c*128 + k4*4);
        Ws[(k4*4+0)*LDS_W + c] = w4.x;
        Ws[(k4*4+1)*LDS_W + c] = w4.y;
        Ws[(k4*4+2)*LDS_W + c] = w4.z;
        Ws[(k4*4+3)*LDS_W + c] = w4.w;
    }
    __syncthreads();

    int tx = tid & 15, ty = tid >> 4;   // 16x16 threads, 8 rows x 8 cols each
    float acc[8][8];
    #pragma unroll
    for (int i = 0; i < 8; i++)
        #pragma unroll
        for (int j = 0; j < 8; j++) acc[i][j] = 0.f;

    #pragma unroll 2
    for (int kk = 0; kk < 128; kk += 4) {
        float4 a4[8];
        #pragma unroll
        for (int i = 0; i < 8; i++)
            a4[i] = *reinterpret_cast<const float4*>(Xs + (ty*8 + i)*LDS_X + kk);
        #pragma unroll
        for (int q = 0; q < 4; q++) {
            float4 b0 = *reinterpret_cast<const float4*>(Ws + (kk+q)*LDS_W + tx*4);
            float4 b1 = *reinterpret_cast<const float4*>(Ws + (kk+q)*LDS_W + 64 + tx*4);
            #pragma unroll
            for (int i = 0; i < 8; i++) {
                float av = (q == 0) ? a4[i].x : (q == 1) ? a4[i].y : (q == 2) ? a4[i].z : a4[i].w;
                acc[i][0] += av*b0.x; acc[i][1] += av*b0.y;
                acc[i][2] += av*b0.z; acc[i][3] += av*b0.w;
                acc[i][4] += av*b1.x; acc[i][5] += av*b1.y;
                acc[i][6] += av*b1.z; acc[i][7] += av*b1.w;
            }
        }
    }

    float aSv[8], aDv[8];
    #pragma unroll
    for (int j = 0; j < 4; j++) {
        aSv[j]   = aS[tx*4 + j];      aSv[4+j] = aS[64 + tx*4 + j];
        aDv[j]   = aD[tx*4 + j];      aDv[4+j] = aD[64 + tx*4 + j];
    }
    int lane = tid & 31;
    #pragma unroll
    for (int i = 0; i < 8; i++) {
        int r = rowBase + ty*8 + i;
        bool ok = (r < M);
        if (ok) {
            *reinterpret_cast<float4*>(Y + (size_t)r*128 + tx*4) =
                make_float4(acc[i][0], acc[i][1], acc[i][2], acc[i][3]);
            *reinterpret_cast<float4*>(Y + (size_t)r*128 + 64 + tx*4) =
                make_float4(acc[i][4], acc[i][5], acc[i][6], acc[i][7]);
        }
        float pa = 0.f, pd = 0.f;
        #pragma unroll
        for (int j = 0; j < 8; j++) { pa += acc[i][j]*aSv[j]; pd += acc[i][j]*aDv[j]; }
        #pragma unroll
        for (int o = 8; o > 0; o >>= 1) {
            pa += __shfl_xor_sync(0xffffffffu, pa, o);
            pd += __shfl_xor_sync(0xffffffffu, pd, o);
        }
        if (ok && (lane & 15) == 0) { asv[r] = pa; adv[r] = pd; }
    }
}

// ---------------- GAT aggregation + fused pooling score ----------------
__global__ void gat_agg_k(const float* __restrict__ hl, const float* __restrict__ asv,
                          const float* __restrict__ adv, const int* __restrict__ adj,
                          const int* __restrict__ deg, const float* __restrict__ b,
                          float* __restrict__ out, int N,
                          const float* __restrict__ p, const float* __restrict__ nrm,
                          int nidx, float* __restrict__ sc)
{
    int d = (blockIdx.x*blockDim.x + threadIdx.x) >> 5;
    int lane = threadIdx.x & 31;
    if (d >= N) return;
    float add = adv[d];
    float l = asv[d] + add; l = (l > 0.f) ? l : 0.2f*l;
    float w = __expf(l);
    float den0 = w, den1 = 0.f;
    float4 hv = *reinterpret_cast<const float4*>(hl + (size_t)d*128 + lane*4);
    float4 a0 = make_float4(w*hv.x, w*hv.y, w*hv.z, w*hv.w);
    float4 a1 = make_float4(0.f, 0.f, 0.f, 0.f);
    int dg = deg[d]; if (dg > CAP) dg = CAP;
    const int* row = adj + (size_t)d*CAP;
    int j = 0;
    for (; j + 4 <= dg; j += 4) {
        int4 s4 = *reinterpret_cast<const int4*>(row + j);
        float l0 = asv[s4.x] + add; l0 = (l0 > 0.f) ? l0 : 0.2f*l0;
        float l1 = asv[s4.y] + add; l1 = (l1 > 0.f) ? l1 : 0.2f*l1;
        float l2 = asv[s4.z] + add; l2 = (l2 > 0.f) ? l2 : 0.2f*l2;
        float l3 = asv[s4.w] + add; l3 = (l3 > 0.f) ? l3 : 0.2f*l3;
        float w0 = __expf(l0), w1 = __expf(l1), w2 = __expf(l2), w3 = __expf(l3);
        float4 g0 = *reinterpret_cast<const float4*>(hl + (size_t)s4.x*128 + lane*4);
        float4 g1 = *reinterpret_cast<const float4*>(hl + (size_t)s4.y*128 + lane*4);
        float4 g2 = *reinterpret_cast<const float4*>(hl + (size_t)s4.z*128 + lane*4);
        float4 g3 = *reinterpret_cast<const float4*>(hl + (size_t)s4.w*128 + lane*4);
        den0 += w0 + w2; den1 += w1 + w3;
        a0.x += w0*g0.x; a0.y += w0*g0.y; a0.z += w0*g0.z; a0.w += w0*g0.w;
        a1.x += w1*g1.x; a1.y += w1*g1.y; a1.z += w1*g1.z; a1.w += w1*g1.w;
        a0.x += w2*g2.x; a0.y += w2*g2.y; a0.z += w2*g2.z; a0.w += w2*g2.w;
        a1.x += w3*g3.x; a1.y += w3*g3.y; a1.z += w3*g3.z; a1.w += w3*g3.w;
    }
    for (; j < dg; j++) {
        int s0 = row[j];
        float l0 = asv[s0] + add; l0 = (l0 > 0.f) ? l0 : 0.2f*l0;
        float w0 = __expf(l0);
        float4 g0 = *reinterpret_cast<const float4*>(hl + (size_t)s0*128 + lane*4);
        den0 += w0;
        a0.x += w0*g0.x; a0.y += w0*g0.y; a0.z += w0*g0.z; a0.w += w0*g0.w;
    }
    float inv = 1.f/(den0 + den1);
    float4 bb = *reinterpret_cast<const float4*>(b + lane*4);
    float4 o;
    o.x = fmaxf((a0.x + a1.x)*inv + bb.x, 0.f);
    o.y = fmaxf((a0.y + a1.y)*inv + bb.y, 0.f);
    o.z = fmaxf((a0.z + a1.z)*inv + bb.z, 0.f);
    o.w = fmaxf((a0.w + a1.w)*inv + bb.w, 0.f);
    *reinterpret_cast<float4*>(out + (size_t)d*128 + lane*4) = o;
    float4 p4 = *reinterpret_cast<const float4*>(p + lane*4);
    float s = o.x*p4.x + o.y*p4.y + o.z*p4.z + o.w*p4.w;
    #pragma unroll
    for (int off = 16; off > 0; off >>= 1) s += __shfl_xor_sync(0xffffffffu, s, off);
    if (lane == 0) sc[d] = s * nrm[nidx];
}

// ---------------- fused per-graph pool: radix-select topk + readout + build (+mlp) ---
// modes 1/2: grid = 2*G_NUM. role 0 = readout + perm/gsc emit; role 1 = adjacency build.
// mode 3:    grid = G_NUM, role 0 only; readout + final MLP, no build, no perm.
__global__ void __launch_bounds__(1024, 1)
pool_k(const float* __restrict__ sc, const float* __restrict__ h,
       float* __restrict__ z,
       const int* __restrict__ srcRaw, const int* __restrict__ dstRaw, int ePer,
       const int2* __restrict__ listIn, const int* __restrict__ cntIn,
       int2* __restrict__ listOut, int* __restrict__ cntOut,
       int* __restrict__ deg, int* __restrict__ adj,
       int* __restrict__ permOut, float* __restrict__ gscOut,
       int n, int k, int mode,
       const float* __restrict__ lw1, const float* __restrict__ lb1,
       const float* __restrict__ lw2, const float* __restrict__ lb2,
       const float* __restrict__ lw3, const float* __restrict__ lb3,
       float* __restrict__ out)
{
    __shared__ unsigned skey[1024];
    __shared__ float sval[1024];
    __shared__ int   sidx[1024];      // new-id -> old local index
    __shared__ int   smap[NPER];      // old local index -> new-id or -1
    __shared__ int   sdeg[K1];
    __shared__ float sgsc[K1];
    __shared__ int   hist8[8*256];    // round-1 sub-histograms
    __shared__ int   hist[256];
    __shared__ int   sfx[256];        // sfx[b] = #keys with bin >= b
    __shared__ int   wOff[32];
    __shared__ unsigned s_prefix;
    __shared__ int   s_need;
    __shared__ float rmax[1024], rsum[1024];
    __shared__ float zr[256], t1v[128], t2v[64], ov[10], red[2];

    int g, role;
    if (mode == 3) { g = blockIdx.x; role = 0; }
    else           { g = blockIdx.x >> 1; role = blockIdx.x & 1; }
    int t = threadIdx.x;
    int wid = t >> 5, lane = t & 31;
    unsigned lmask = (1u << lane) - 1u;

    // ---- load scores + zero round-1 sub-histograms ----
    if (t < n) {
        float v = sc[g*n + t];
        sval[t] = v;
        skey[t] = f2key(v);
        smap[t] = -1;
    } else if (t < 1024) {
        skey[t] = 0u; sval[t] = -FINF;
    }
    hist8[t] = 0; hist8[t + 1024] = 0;
    if (t < K1) sdeg[t] = 0;
    __syncthreads();

    // ---- 4-round radix select: threshold key T, tie-count need ----
    unsigned prefix = 0; int need = k;
    for (int shift = 24; shift >= 0; shift -= 8) {
        if (shift == 24) {
            if (t < n) atomicAdd(&hist8[(wid & 7)*256 + (skey[t] >> 24)], 1);
        } else {
            if (t < 256) hist[t] = 0;
            __syncthreads();
            if (t < n) {
                unsigned key = skey[t];
                if ((key >> (shift+8)) == (prefix >> (shift+8)))
                    atomicAdd(&hist[(key >> shift) & 255], 1);
            }
        }
        __syncthreads();
        // warp-0 suffix scan over 256 bins (lane owns bins [8*lane, 8*lane+8))
        if (wid == 0) {
            int base = lane*8;
            int v[8]; int cs = 0;
            #pragma unroll
            for (int j = 0; j < 8; j++) {
                int hv;
                if (shift == 24) {
                    hv = 0;
                    #pragma unroll
                    for (int s8 = 0; s8 < 8; s8++) hv += hist8[s8*256 + base + j];
                } else hv = hist[base + j];
                v[j] = hv; cs += hv;
            }
            int suf = cs;
            #pragma unroll
            for (int o = 1; o < 32; o <<= 1) {
                int u = __shfl_down_sync(0xffffffffu, suf, o);
                if (lane + o < 32) suf += u;
            }
            int run = suf - cs;          // sum over lanes > lane
            #pragma unroll
            for (int j = 7; j >= 0; j--) { run += v[j]; sfx[base + j] = run; }
        }
        __syncthreads();
        if (t < 256) {
            int b = t;
            int Sb  = sfx[b];                       // keys with bin >= b
            int Sb1 = (b == 255) ? 0 : sfx[b + 1];  // keys with bin >  b
            if (Sb1 < need && need <= Sb) {
                s_prefix = prefix | ((unsigned)b << shift);
                s_need   = need - Sb1;
            }
        }
        __syncthreads();
        prefix = s_prefix; need = s_need;
        __syncthreads();
    }
    const unsigned T = prefix;

    // ---- deterministic selection: key>T, plus first `need` key==T by index ----
    bool eq = false, gt = false;
    if (t < n) {
        unsigned key = skey[t];
        gt = (key > T);
        eq = (key == T);
    }
    unsigned beq = __ballot_sync(0xffffffffu, eq);
    int eqInWarp = __popc(beq & lmask);
    if (lane == 0) wOff[wid] = __popc(beq);
    __syncthreads();
    if (wid == 0) {
        int v = wOff[lane];
        int inc = v;
        #pragma unroll
        for (int o = 1; o < 32; o <<= 1) {
            int u = __shfl_up_sync(0xffffffffu, inc, o);
            if (lane >= o) inc += u;
        }
        wOff[lane] = inc - v;
    }
    __syncthreads();
    int tieRank = wOff[wid] + eqInWarp;
    bool sel = gt || (eq && tieRank < need);
    __syncthreads();

    unsigned bsel = __ballot_sync(0xffffffffu, sel);
    int selInWarp = __popc(bsel & lmask);
    if (lane == 0) wOff[wid] = __popc(bsel);
    __syncthreads();
    if (wid == 0) {
        int v = wOff[lane];
        int inc = v;
        #pragma unroll
        for (int o = 1; o < 32; o <<= 1) {
            int u = __shfl_up_sync(0xffffffffu, inc, o);
            if (lane >= o) inc += u;
        }
        wOff[lane] = inc - v;
    }
    __syncthreads();
    if (sel) {
        int newid = wOff[wid] + selInWarp;   // 0..k-1, index-ordered
        smap[t] = newid;
        sidx[newid] = t;
        sgsc[newid] = tanhf(sval[t]);
    }
    __syncthreads();

    if (role == 0) {
        // ---- emit perm/gsc for the next GEMM's fused gather (modes 1,2) ----
        if (mode != 3 && t < k) {
            permOut[g*k + t] = g*n + sidx[t];
            gscOut[g*k + t]  = sgsc[t];
        }

        // ---- readout directly from h * gsc: columns 0..127, 8 row-chunks ----
        {
            int c = t & 127, ch = t >> 7;
            int per = (k + 7) >> 3;
            int r0 = ch*per, r1 = r0 + per; if (r1 > k) r1 = k;
            float m = -FINF, s = 0.f;
            for (int r = r0; r < r1; r++) {
                float v = h[((size_t)(g*n + sidx[r]))*128 + c] * sgsc[r];
                m = fmaxf(m, v); s += v;
            }
            rmax[ch*128 + c] = m; rsum[ch*128 + c] = s;
        }
        __syncthreads();
        if (t < 128) {
            float m = -FINF, s = 0.f;
            #pragma unroll
            for (int ch = 0; ch < 8; ch++) { m = fmaxf(m, rmax[ch*128 + t]); s += rsum[ch*128 + t]; }
            if (mode == 1) {
                z[g*256 + t]       = m;
                z[g*256 + 128 + t] = s / (float)k;
            } else {
                z[g*256 + t]       += m;
                z[g*256 + 128 + t] += s / (float)k;
            }
        }
        if (mode == 3) {
            // ---- final MLP + log_softmax ----
            __syncthreads();
            if (t < 256) zr[t] = z[g*256 + t];
            __syncthreads();
            if (t < 128) {
                float a = lb1[t];
                const float* w = lw1 + t*256;
                for (int j = 0; j < 256; j++) a += zr[j]*w[j];
                t1v[t] = fmaxf(a, 0.f);
            }
            __syncthreads();
            if (t < 64) {
                float a = lb2[t];
                const float* w = lw2 + t*128;
                for (int j = 0; j < 128; j++) a += t1v[j]*w[j];
                t2v[t] = fmaxf(a, 0.f);
            }
            __syncthreads();
            if (t < 10) {
                float a = lb3[t];
                const float* w = lw3 + t*64;
                for (int j = 0; j < 64; j++) a += t2v[j]*w[j];
                ov[t] = a;
            }
            __syncthreads();
            if (t == 0) {
                float m = -FINF;
                for (int i = 0; i < 10; i++) m = fmaxf(m, ov[i]);
                float s = 0.f;
                for (int i = 0; i < 10; i++) s += expf(ov[i] - m);
                red[0] = m; red[1] = logf(s);
            }
            __syncthreads();
            if (t < 10) out[g*10 + t] = ov[t] - red[0] - red[1];
        }
    } else if (mode == 1) {
        // ---- raw-edge build + per-warp survivor-list segments (no smem atomics) ----
        int base = g*ePer;
        int2* seg = listOut + ((size_t)(g*32 + wid))*SEG;
        int lc = 0;                        // per-warp segment fill (uniform across warp)
        int iters = (ePer + 1023) >> 10;   // uniform trip count for ALL threads
        for (int it = 0; it < iters; it++) {
            int e0 = t + (it << 10);
            bool act = (e0 < ePer);
            int sn = -1, dn = -1;
            if (act) {
                int s = srcRaw[base + e0] - g*n;
                int d = dstRaw[base + e0] - g*n;
                sn = smap[s]; dn = smap[d];
            }
            bool ok = act && sn >= 0 && dn >= 0;
            if (ok) {
                int pos = atomicAdd(&sdeg[dn], 1);
                if (pos < CAP) adj[((size_t)(g*k + dn))*CAP + pos] = g*k + sn;
            }
            unsigned mask = __ballot_sync(0xffffffffu, ok);
            if (ok) {
                int off = lc + __popc(mask & lmask);
                if (off < SEG) seg[off] = make_int2(sn, dn);
            }
            lc += __popc(mask);
        }
        if (lane == 0) cntOut[g*32 + wid] = (lc < SEG) ? lc : SEG;
        __syncthreads();
        if (t < k) deg[g*k + t] = sdeg[t];
    } else {
        // ---- mode 2: per-warp-segment list build (warp w consumes segment w) ----
        {
            int cnt = cntIn[g*32 + wid];
            const int2* seg = listIn + ((size_t)(g*32 + wid))*SEG;
            for (int e = lane; e < cnt; e += 32) {
                int2 sd = seg[e];
                int sn = smap[sd.x], dn = smap[sd.y];
                if (sn >= 0 && dn >= 0) {
                    int pos = atomicAdd(&sdeg[dn], 1);
                    if (pos < CAP) adj[((size_t)(g*k + dn))*CAP + pos] = g*k + sn;
                }
            }
        }
        __syncthreads();
        if (t < k) deg[g*k + t] = sdeg[t];
    }
}

// ---------------- host driver ----------------
static inline int cdiv(int a, int b) { return (a + b - 1) / b; }

extern "C" void kernel_launch(void* const* d_in, const int* in_sizes, int n_in,
                              void* d_out, int out_size)
{
    const float* x   = (const float*)d_in[0];
    const int*   ei  = (const int*)  d_in[1];
    const float* W1  = (const float*)d_in[2];
    const float* aS1 = (const float*)d_in[3];
    const float* aD1 = (const float*)d_in[4];
    const float* b1  = (const float*)d_in[5];
    const float* W2  = (const float*)d_in[6];
    const float* aS2 = (const float*)d_in[7];
    const float* aD2 = (const float*)d_in[8];
    const float* b2  = (const float*)d_in[9];
    const float* W3  = (const float*)d_in[10];
    const float* aS3 = (const float*)d_in[11];
    const float* aD3 = (const float*)d_in[12];
    const float* b3  = (const float*)d_in[13];
    const float* p1  = (const float*)d_in[14];
    const float* p2  = (const float*)d_in[15];
    const float* lw1 = (const float*)d_in[16];
    const float* lb1 = (const float*)d_in[17];
    const float* lw2 = (const float*)d_in[18];
    const float* lb2 = (const float*)d_in[19];
    const float* lw3 = (const float*)d_in[20];
    const float* lb3 = (const float*)d_in[21];
    float* out = (float*)d_out;

    const int E = in_sizes[1] / 2;
    const int EPER = E / G_NUM;

    void *p_hl, *p_h, *p_as, *p_ad, *p_sc, *p_deg, *p_adj;
    void *p_list, *p_cnt, *p_perm, *p_gsc, *p_z, *p_nrm;
    cudaGetSymbolAddress(&p_hl, g_hl);   cudaGetSymbolAddress(&p_h, g_h);
    cudaGetSymbolAddress(&p_as, g_as);   cudaGetSymbolAddress(&p_ad, g_ad);
    cudaGetSymbolAddress(&p_sc, g_sc);
    cudaGetSymbolAddress(&p_deg, g_deg); cudaGetSymbolAddress(&p_adj, g_adj);
    cudaGetSymbolAddress(&p_list, g_list); cudaGetSymbolAddress(&p_cnt, g_cnt);
    cudaGetSymbolAddress(&p_perm, g_permA); cudaGetSymbolAddress(&p_gsc, g_gscA);
    cudaGetSymbolAddress(&p_z, g_z);       cudaGetSymbolAddress(&p_nrm, g_norms);

    float* hl  = (float*)p_hl;  float* h   = (float*)p_h;
    float* asv = (float*)p_as;  float* adv = (float*)p_ad;  float* sc = (float*)p_sc;
    int* deg = (int*)p_deg;     int* adj = (int*)p_adj;
    int2* lst = (int2*)p_list;  int* cnt = (int*)p_cnt;
    int* perm = (int*)p_perm;   float* gsc = (float*)p_gsc;
    float* z = (float*)p_z;     float* nrm = (float*)p_nrm;

    cudaFuncSetAttribute(gemm128_k, cudaFuncAttributeMaxDynamicSharedMemorySize, GEMM_SMEM);

    const int EB = cdiv(E, 1024);

    // ---------- stage 1 ----------
    cudaMemsetAsync(deg, 0, (size_t)N1*sizeof(int));
    init_k<<<EB, 256>>>(p1, p2, nrm, ei, ei + E, E, deg, adj);
    gemm128_k<<<cdiv(N1, 128), 256, GEMM_SMEM>>>(x, W1, hl, N1, aS1, aD1, asv, adv,
                                                 nullptr, nullptr);
    gat_agg_k<<<cdiv(N1, 8), 256>>>(hl, asv, adv, adj, deg, b1, h, N1, p1, nrm, 0, sc);
    pool_k<<<2*G_NUM, 1024>>>(sc, h, z, ei, ei + E, EPER,
                              nullptr, nullptr, lst, cnt, deg, adj, perm, gsc,
                              NPER, K1, 1,
                              lw1, lb1, lw2, lb2, lw3, lb3, nullptr);

    // ---------- stage 2 ----------
    gemm128_k<<<cdiv(N2, 128), 256, GEMM_SMEM>>>(h, W2, hl, N2, aS2, aD2, asv, adv,
                                                 perm, gsc);
    gat_agg_k<<<cdiv(N2, 8), 256>>>(hl, asv, adv, adj, deg, b2, h, N2, p2, nrm, 1, sc);
    pool_k<<<2*G_NUM, 1024>>>(sc, h, z, nullptr, nullptr, EPER,
                              lst, cnt, nullptr, nullptr, deg, adj, perm, gsc,
                              K1, K2, 2,
                              lw1, lb1, lw2, lb2, lw3, lb3, nullptr);

    // ---------- stage 3 ----------
    gemm128_k<<<cdiv(N3, 128), 256, GEMM_SMEM>>>(h, W3, hl, N3, aS3, aD3, asv, adv,
                                                 perm, gsc);
    gat_agg_k<<<cdiv(N3, 8), 256>>>(hl, asv, adv, adj, deg, b3, h, N3, p2, nrm, 1, sc);
    pool_k<<<G_NUM, 1024>>>(sc, h, z, nullptr, nullptr, EPER,
                            nullptr, nullptr, nullptr, nullptr, nullptr, nullptr,
                            nullptr, nullptr,
                            K2, K3, 3,
                            lw1, lb1, lw2, lb2, lw3, lb3, out);
}